// round 2
// baseline (speedup 1.0000x reference)
#include <cuda_runtime.h>
#include <math.h>

#define B_TOTAL 16384
#define D_IN    512
#define HID     128
#define NTREE   64
#define NNODES  63
#define NCLS    10

// -------- scratch (device globals; no allocation allowed) --------
__device__ float g_xc[B_TOTAL * D_IN];      // NaN-cleaned x
__device__ int   g_missing[B_TOTAL];        // any-NaN per row
__device__ float g_attn[NTREE * B_TOTAL];   // [t][b] = softmax(attn)*0.3*resw[t]

// ================= kernel 0: clean NaNs =================
__global__ void k_clean(const float* __restrict__ x) {
    int row = blockIdx.x;
    int q = threadIdx.x;  // 128 quads of 4 floats = 512
    __shared__ int flag;
    if (q == 0) flag = 0;
    __syncthreads();
    float4 v = reinterpret_cast<const float4*>(x)[row * 128 + q];
    int m = 0;
    if (v.x != v.x) { v.x = 0.f; m = 1; }
    if (v.y != v.y) { v.y = 0.f; m = 1; }
    if (v.z != v.z) { v.z = 0.f; m = 1; }
    if (v.w != v.w) { v.w = 0.f; m = 1; }
    if (m) atomicOr(&flag, 1);
    reinterpret_cast<float4*>(g_xc)[row * 128 + q] = v;
    __syncthreads();
    if (q == 0) g_missing[row] = flag;
}

// ================= kernel A: attention =================
// CTA = 64 rows, 256 threads. Phase1: h = BN(relu(x@W1+b1)); Phase2: logits = h@W2+b2;
// row softmax -> g_attn[t][b] = attn * (0.3*resw[t])
__global__ __launch_bounds__(256) void k_attn(
    const float* __restrict__ x,
    const float* __restrict__ w1, const float* __restrict__ b1,
    const float* __restrict__ gamma_, const float* __restrict__ beta_,
    const float* __restrict__ mean_, const float* __restrict__ var_,
    const float* __restrict__ w2, const float* __restrict__ b2,
    const float* __restrict__ resw)
{
    __shared__ __align__(16) char smem[33792];
    float4* xs4  = reinterpret_cast<float4*>(smem);           // [64][9] quads (32 k)
    float*  xsf  = reinterpret_cast<float*>(smem);
    float4* w1s4 = reinterpret_cast<float4*>(smem + 9216);    // [32][33] quads
    float4* hs4  = reinterpret_cast<float4*>(smem);           // phase2: [64][33] quads
    float*  hsf  = reinterpret_cast<float*>(smem);
    float*  ls   = reinterpret_cast<float*>(smem);            // softmax: [64][68] floats

    const int tx = threadIdx.x;
    const int row0 = blockIdx.x * 64;
    const int ct = tx & 15, rt = tx >> 4;    // 16 col-groups x 16 row-groups
    const int c0 = ct * 8,  r0 = rt * 4;     // 8 cols, 4 rows per thread

    float acc[4][8];
#pragma unroll
    for (int i = 0; i < 4; ++i)
#pragma unroll
        for (int j = 0; j < 8; ++j) acc[i][j] = 0.f;

    const float4* x4  = reinterpret_cast<const float4*>(x);
    const float4* w14 = reinterpret_cast<const float4*>(w1);

    for (int kc = 0; kc < 16; ++kc) {        // K chunks of 32
#pragma unroll
        for (int j = 0; j < 2; ++j) {        // xs: 64 rows x 8 quads
            int idx = tx + 256 * j;
            int r = idx >> 3, q = idx & 7;
            xs4[r * 9 + q] = x4[(row0 + r) * 128 + kc * 8 + q];
        }
#pragma unroll
        for (int j = 0; j < 4; ++j) {        // w1: 32 k-rows x 32 quads
            int idx = tx + 256 * j;
            int k = idx >> 5, cq = idx & 31;
            w1s4[k * 33 + cq] = w14[(kc * 32 + k) * 32 + cq];
        }
        __syncthreads();
#pragma unroll 4
        for (int kk = 0; kk < 32; ++kk) {
            float4 bq0 = w1s4[kk * 33 + ct * 2];
            float4 bq1 = w1s4[kk * 33 + ct * 2 + 1];
#pragma unroll
            for (int i = 0; i < 4; ++i) {
                float a = xsf[(r0 + i) * 36 + kk];
                acc[i][0] += a * bq0.x; acc[i][1] += a * bq0.y;
                acc[i][2] += a * bq0.z; acc[i][3] += a * bq0.w;
                acc[i][4] += a * bq1.x; acc[i][5] += a * bq1.y;
                acc[i][6] += a * bq1.z; acc[i][7] += a * bq1.w;
            }
        }
        __syncthreads();
    }

    // epilogue: +b1, relu, BN -> hs (aliases xs/w1s; safe after final sync)
    float sc[8], sh[8], bb[8];
#pragma unroll
    for (int j = 0; j < 8; ++j) {
        int c = c0 + j;
        float s = gamma_[c] * rsqrtf(var_[c] + 1e-5f);
        sc[j] = s;
        sh[j] = beta_[c] - mean_[c] * s;
        bb[j] = b1[c];
    }
#pragma unroll
    for (int i = 0; i < 4; ++i) {
        float h[8];
#pragma unroll
        for (int j = 0; j < 8; ++j) {
            float v = fmaxf(acc[i][j] + bb[j], 0.f);
            h[j] = v * sc[j] + sh[j];
        }
        hs4[(r0 + i) * 33 + ct * 2]     = make_float4(h[0], h[1], h[2], h[3]);
        hs4[(r0 + i) * 33 + ct * 2 + 1] = make_float4(h[4], h[5], h[6], h[7]);
    }
    __syncthreads();

    // phase 2: logits2[64][64] = hs @ W2 + b2
    const int tt = tx & 15, rt2 = tx >> 4;
    const int t0 = tt * 4, r0b = rt2 * 4;
    float a2[4][4];
#pragma unroll
    for (int i = 0; i < 4; ++i)
#pragma unroll
        for (int j = 0; j < 4; ++j) a2[i][j] = b2[t0 + j];
    const float4* w24 = reinterpret_cast<const float4*>(w2);
#pragma unroll 4
    for (int c = 0; c < 128; ++c) {
        float4 wv = __ldg(&w24[c * 16 + tt]);
#pragma unroll
        for (int i = 0; i < 4; ++i) {
            float h = hsf[(r0b + i) * 132 + c];
            a2[i][0] += h * wv.x; a2[i][1] += h * wv.y;
            a2[i][2] += h * wv.z; a2[i][3] += h * wv.w;
        }
    }
    __syncthreads();   // all hs reads done before ls overwrites
#pragma unroll
    for (int i = 0; i < 4; ++i)
        *reinterpret_cast<float4*>(&ls[(r0b + i) * 68 + t0]) =
            make_float4(a2[i][0], a2[i][1], a2[i][2], a2[i][3]);
    __syncthreads();

    if (tx < 64) {
        int row = row0 + tx;
        const float* lr = ls + tx * 68;
        float m = -1e30f;
#pragma unroll 4
        for (int t = 0; t < 64; ++t) m = fmaxf(m, lr[t]);
        float s = 0.f;
#pragma unroll 4
        for (int t = 0; t < 64; ++t) s += expf(lr[t] - m);
        float inv = 1.f / s;
#pragma unroll 4
        for (int t = 0; t < 64; ++t)
            g_attn[t * B_TOTAL + row] = expf(lr[t] - m) * inv * (0.3f * resw[t]);
    }
}

// ================= kernel B: fused trees =================
// CTA = 64 rows, 128 threads. Loops 64 trees: logits GEMM (64x64x512) ->
// sigmoid -> routing products -> leaf reduction -> weighted accumulate -> softmax.
__global__ __launch_bounds__(128) void k_trees(
    const float* __restrict__ tree_w,
    const float* __restrict__ tree_b,
    const float* __restrict__ tree_temp,
    const float* __restrict__ leaf_values,
    float* __restrict__ out)
{
    __shared__ __align__(16) char smem[17408 * 2 + 3072];
    float4* xs4   = reinterpret_cast<float4*>(smem);            // [64][17] quads
    float*  dec_s = reinterpret_cast<float*>(smem);             // [64][68] floats (alias xs4)
    float4* ws4   = reinterpret_cast<float4*>(smem + 17408);    // [64][17] quads
    float*  leaf_s = reinterpret_cast<float*>(smem + 34816);    // [64][12] floats

    const int tx = threadIdx.x;
    const int row0 = blockIdx.x * 64;
    const int nt = tx & 15, rt = tx >> 4;   // 16 node-groups x 8 row-groups
    const int n0 = nt * 4,  r0 = rt * 8;    // 4 nodes, 8 rows per thread

    const float4* xc4 = reinterpret_cast<const float4*>(g_xc);
    const float4* tw4 = reinterpret_cast<const float4*>(tree_w);

    int miss[8];
#pragma unroll
    for (int i = 0; i < 8; ++i) miss[i] = g_missing[row0 + r0 + i];

    float pred[NCLS];
#pragma unroll
    for (int c = 0; c < NCLS; ++c) pred[c] = 0.f;

    for (int t = 0; t < NTREE; ++t) {
        // leaf values for this tree: 64 x 10 (pitch 12)
#pragma unroll
        for (int j = 0; j < 5; ++j) {
            int idx = tx + 128 * j;
            int L = idx / 10, c = idx - L * 10;
            leaf_s[L * 12 + c] = leaf_values[t * 640 + idx];
        }
        float invtemp = 1.f / tree_temp[t];

        float acc[8][4];
#pragma unroll
        for (int i = 0; i < 8; ++i)
#pragma unroll
            for (int j = 0; j < 4; ++j) acc[i][j] = 0.f;

        for (int kc = 0; kc < 8; ++kc) {     // K chunks of 64 (16 quads)
#pragma unroll
            for (int j = 0; j < 8; ++j) {    // xs: 64 rows x 16 quads
                int idx = tx + 128 * j;
                int r = idx >> 4, q = idx & 15;
                xs4[r * 17 + q] = xc4[(row0 + r) * 128 + kc * 16 + q];
            }
#pragma unroll
            for (int j = 0; j < 8; ++j) {    // ws: 64 nodes (63 real) x 16 quads
                int idx = tx + 128 * j;
                int n = idx >> 4, q = idx & 15;
                float4 v = make_float4(0.f, 0.f, 0.f, 0.f);
                if (n < NNODES) v = tw4[(t * NNODES + n) * 128 + kc * 16 + q];
                ws4[n * 17 + q] = v;
            }
            __syncthreads();
#pragma unroll
            for (int kq = 0; kq < 16; ++kq) {
                float4 w0 = ws4[(n0 + 0) * 17 + kq];
                float4 w1_ = ws4[(n0 + 1) * 17 + kq];
                float4 w2_ = ws4[(n0 + 2) * 17 + kq];
                float4 w3 = ws4[(n0 + 3) * 17 + kq];
#pragma unroll
                for (int i = 0; i < 8; ++i) {
                    float4 xv = xs4[(r0 + i) * 17 + kq];
                    acc[i][0] += xv.x * w0.x + xv.y * w0.y + xv.z * w0.z + xv.w * w0.w;
                    acc[i][1] += xv.x * w1_.x + xv.y * w1_.y + xv.z * w1_.z + xv.w * w1_.w;
                    acc[i][2] += xv.x * w2_.x + xv.y * w2_.y + xv.z * w2_.z + xv.w * w2_.w;
                    acc[i][3] += xv.x * w3.x + xv.y * w3.y + xv.z * w3.z + xv.w * w3.w;
                }
            }
            __syncthreads();
        }

        // sigmoid epilogue -> dec_s (aliases xs4; safe: past last sync all tile reads done)
        float bnv[4];
#pragma unroll
        for (int j = 0; j < 4; ++j)
            bnv[j] = (n0 + j < NNODES) ? tree_b[t * NNODES + n0 + j] : 0.f;
#pragma unroll
        for (int i = 0; i < 8; ++i) {
            float dv[4];
#pragma unroll
            for (int j = 0; j < 4; ++j) {
                float z = (acc[i][j] + bnv[j]) * invtemp;
                z = fminf(fmaxf(z, -30.f), 30.f);
                float e = __expf(-z);
                dv[j] = __fdividef(1.f, 1.f + e);
                if (miss[i]) dv[j] = 0.5f;
            }
            *reinterpret_cast<float4*>(&dec_s[(r0 + i) * 68 + n0]) =
                make_float4(dv[0], dv[1], dv[2], dv[3]);
        }
        __syncthreads();

        // routing + leaf reduction: one thread per row
        if (tx < 64) {
            const float* dp = dec_s + tx * 68;
            float ac = g_attn[t * B_TOTAL + row0 + tx];
            float r2[2], r4[4], r8[8], r16[16], r32[32];
            float d = dp[0];
            r2[0] = d; r2[1] = 1.f - d;
#pragma unroll
            for (int i = 0; i < 2; ++i) { d = dp[1 + i];  r4[i] = r2[i] * d;  r4[i + 2]  = r2[i] * (1.f - d); }
#pragma unroll
            for (int i = 0; i < 4; ++i) { d = dp[3 + i];  r8[i] = r4[i] * d;  r8[i + 4]  = r4[i] * (1.f - d); }
#pragma unroll
            for (int i = 0; i < 8; ++i) { d = dp[7 + i];  r16[i] = r8[i] * d; r16[i + 8] = r8[i] * (1.f - d); }
#pragma unroll
            for (int i = 0; i < 16; ++i){ d = dp[15 + i]; r32[i] = r16[i] * d; r32[i + 16] = r16[i] * (1.f - d); }
            float o[NCLS];
#pragma unroll
            for (int c = 0; c < NCLS; ++c) o[c] = 0.f;
#pragma unroll
            for (int i = 0; i < 32; ++i) {
                d = dp[31 + i];
                float pL = r32[i] * d;
                float pR = r32[i] * (1.f - d);
                const float* lL = leaf_s + i * 12;
                const float* lR = leaf_s + (i + 32) * 12;
#pragma unroll
                for (int c = 0; c < NCLS; ++c) o[c] += pL * lL[c] + pR * lR[c];
            }
#pragma unroll
            for (int c = 0; c < NCLS; ++c) pred[c] += ac * o[c];
        }
        __syncthreads();   // protect dec_s/leaf_s before next tree's loads
    }

    if (tx < 64) {
        int row = row0 + tx;
        float m = pred[0];
#pragma unroll
        for (int c = 1; c < NCLS; ++c) m = fmaxf(m, pred[c]);
        float e[NCLS], s = 0.f;
#pragma unroll
        for (int c = 0; c < NCLS; ++c) { e[c] = expf(pred[c] - m); s += e[c]; }
        float inv = 1.f / s;
#pragma unroll
        for (int c = 0; c < NCLS; ++c) out[row * NCLS + c] = e[c] * inv;
    }
}

// ================= launcher =================
extern "C" void kernel_launch(void* const* d_in, const int* in_sizes, int n_in,
                              void* d_out, int out_size) {
    const float* x     = (const float*)d_in[0];
    const float* w1    = (const float*)d_in[1];
    const float* b1    = (const float*)d_in[2];
    const float* gamma_ = (const float*)d_in[3];
    const float* beta_ = (const float*)d_in[4];
    const float* mean_ = (const float*)d_in[5];
    const float* var_  = (const float*)d_in[6];
    const float* w2    = (const float*)d_in[7];
    const float* b2    = (const float*)d_in[8];
    const float* tw    = (const float*)d_in[9];
    const float* tb    = (const float*)d_in[10];
    const float* ttmp  = (const float*)d_in[11];
    const float* lv    = (const float*)d_in[12];
    const float* rw    = (const float*)d_in[13];
    float* out = (float*)d_out;

    k_clean<<<B_TOTAL, 128>>>(x);
    k_attn<<<B_TOTAL / 64, 256>>>(x, w1, b1, gamma_, beta_, mean_, var_, w2, b2, rw);
    k_trees<<<B_TOTAL / 64, 128>>>(tw, tb, ttmp, lv, out);
}